// round 13
// baseline (speedup 1.0000x reference)
#include <cuda_runtime.h>
#include <cstdint>

#define NB   8
#define CDIM 64
#define HH   256
#define WW   256
#define KK   3
#define EPSV 1e-5f
#define RPT  16   // rows per thread in conv

// scratch (allocation-free rule: device globals)
__device__ float g_gap[NB * CDIM];

// evict_last read via createpolicy + cache_hint (legal for .v4.f32)
__device__ __forceinline__ float4 ldg_keep(const float4* p, uint64_t pol) {
    float4 v;
    asm volatile("ld.global.nc.L2::cache_hint.v4.f32 {%0,%1,%2,%3}, [%4], %5;"
                 : "=f"(v.x), "=f"(v.y), "=f"(v.z), "=f"(v.w)
                 : "l"(p), "l"(pol));
    return v;
}

// ---------------- Kernel 1: global average pool per (n,c) plane ----------------
// Reads tagged evict_last: deliberately park x in L2 for the conv pass.
__global__ void gap_kernel(const float* __restrict__ x) {
    int nc = blockIdx.x;                 // 0..511
    uint64_t pol;
    asm("createpolicy.fractional.L2::evict_last.b64 %0, 1.0;" : "=l"(pol));
    const float4* p = (const float4*)(x + (size_t)nc * HH * WW);
    float s = 0.f;
    #pragma unroll 8
    for (int i = threadIdx.x; i < (HH * WW) / 4; i += 512) {
        float4 v = ldg_keep(p + i, pol);
        s += (v.x + v.y) + (v.z + v.w);
    }
    // warp-level reduce, then one smem round over 16 warp sums
    #pragma unroll
    for (int o = 16; o > 0; o >>= 1)
        s += __shfl_down_sync(0xFFFFFFFFu, s, o);
    __shared__ float red[16];
    if ((threadIdx.x & 31) == 0) red[threadIdx.x >> 5] = s;
    __syncthreads();
    if (threadIdx.x < 32) {
        float t = (threadIdx.x < 16) ? red[threadIdx.x] : 0.f;
        #pragma unroll
        for (int o = 8; o > 0; o >>= 1)
            t += __shfl_down_sync(0xFFFFFFFFu, t, o);
        if (threadIdx.x == 0)
            g_gap[nc] = t * (1.0f / (HH * WW));
    }
}

// ---------------- Kernel 2: fused taps + strip conv ----------------
// grid = 2048 blocks (4 per (n,c) plane), 256 threads.
// Reverse plane order vs gap + streaming (__ldcs) last-use reads + streaming
// stores: conv consumes the L2-resident x and never pollutes.
__global__ void __launch_bounds__(256, 6) conv_kernel(
        const float* __restrict__ x, float* __restrict__ out,
        const float* __restrict__ wH, const float* __restrict__ gH,
        const float* __restrict__ bH, const float* __restrict__ mH,
        const float* __restrict__ vH,
        const float* __restrict__ wW, const float* __restrict__ gW,
        const float* __restrict__ bW, const float* __restrict__ mW,
        const float* __restrict__ vW) {
    int plane = (NB * CDIM - 1) - (blockIdx.x >> 2);   // 511..0 (reverse)
    int quart = blockIdx.x & 3;
    int n   = plane >> 6;
    int cch = plane & 63;
    int t = threadIdx.x;
    int g = t & 63;
    int h0 = quart * 64 + (t >> 6) * RPT;

    __shared__ float taps[6];            // [0..2]=H, [3..5]=W
    if (t < 6) {
        int branch = t / 3;              // 0=H, 1=W
        int k = t - branch * 3;
        int row = cch * 3 + k;
        const float* w = branch ? wW : wH;
        const float* gg = branch ? gW : gH;
        const float* bb = branch ? bW : bH;
        const float* mm = branch ? mW : mH;
        const float* vv = branch ? vW : vH;
        const float* gp = g_gap + n * CDIM;
        const float* wr = w + row * CDIM;
        float s = 0.f;
        #pragma unroll
        for (int c = 0; c < CDIM; c++) s += gp[c] * wr[c];
        float f = (s - mm[row]) * (gg[row] * rsqrtf(vv[row] + EPSV)) + bb[row];
        taps[t] = tanhf(f);
    }
    __syncthreads();

    float fh0 = taps[0], fh1 = taps[1], fh2 = taps[2];
    float fw0 = taps[3], fw1 = taps[4], fw2 = taps[5];

    const float4* xp4 = (const float4*)(x + (size_t)plane * HH * WW);
    const float*  xp  = x + (size_t)plane * HH * WW;

    float4* o1 = (float4*)(out + ((size_t)n * 2 * CDIM + cch) * HH * WW);
    float4* o2 = o1 + (size_t)CDIM * HH * WW / 4;

    auto process = [&](int h, const float4& up, const float4& ce, const float4& dn) {
        float xl = (g == 0)  ? ce.y : __ldcs(xp + h * WW + 4 * g - 1);  // reflect left
        float xr = (g == 63) ? ce.z : __ldcs(xp + h * WW + 4 * g + 4);  // reflect right
        float4 h4;
        h4.x = fh0 * xl   + fh1 * ce.x + fh2 * ce.y;
        h4.y = fh0 * ce.x + fh1 * ce.y + fh2 * ce.z;
        h4.z = fh0 * ce.y + fh1 * ce.z + fh2 * ce.w;
        h4.w = fh0 * ce.z + fh1 * ce.w + fh2 * xr;
        float4 v4;
        v4.x = fw0 * up.x + fw1 * ce.x + fw2 * dn.x;
        v4.y = fw0 * up.y + fw1 * ce.y + fw2 * dn.y;
        v4.z = fw0 * up.z + fw1 * ce.z + fw2 * dn.z;
        v4.w = fw0 * up.w + fw1 * ce.w + fw2 * dn.w;
        __stcs(&o1[h * (WW / 4) + g], h4);   // streaming: don't evict x from L2
        __stcs(&o2[h * (WW / 4) + g], v4);
    };

    // rolling window: u = row h-1, cc = row h
    int hu = (h0 == 0) ? 1 : h0 - 1;         // reflect top
    float4 u  = __ldcs(xp4 + hu * (WW / 4) + g);
    float4 cc = __ldcs(xp4 + h0 * (WW / 4) + g);

    #pragma unroll
    for (int hb = 0; hb < RPT; hb += 4) {
        int h = h0 + hb;
        int r1 = h + 1, r2 = h + 2, r3 = h + 3, r4 = h + 4;
        if (r4 > HH - 1) r4 = HH - 2;        // reflect bottom (only last batch)
        if (r3 > HH - 1) r3 = HH - 2;
        // 4 independent vector loads -> MLP 4
        float4 d0 = __ldcs(xp4 + r1 * (WW / 4) + g);
        float4 d1 = __ldcs(xp4 + r2 * (WW / 4) + g);
        float4 d2 = __ldcs(xp4 + r3 * (WW / 4) + g);
        float4 d3 = __ldcs(xp4 + r4 * (WW / 4) + g);

        process(h,     u,  cc, d0);
        process(h + 1, cc, d0, d1);
        process(h + 2, d0, d1, d2);
        process(h + 3, d1, d2, d3);

        u  = d2;
        cc = d3;
    }
}

extern "C" void kernel_launch(void* const* d_in, const int* in_sizes, int n_in,
                              void* d_out, int out_size) {
    const float* x  = (const float*)d_in[0];
    const float* wH = (const float*)d_in[1];
    const float* gH = (const float*)d_in[2];
    const float* bH = (const float*)d_in[3];
    const float* mH = (const float*)d_in[4];
    const float* vH = (const float*)d_in[5];
    const float* wW = (const float*)d_in[6];
    const float* gW = (const float*)d_in[7];
    const float* bW = (const float*)d_in[8];
    const float* mW = (const float*)d_in[9];
    const float* vW = (const float*)d_in[10];
    float* out = (float*)d_out;

    gap_kernel<<<NB * CDIM, 512>>>(x);
    conv_kernel<<<4 * NB * CDIM, 256>>>(x, out, wH, gH, bH, mH, vH,
                                        wW, gW, bW, mW, vW);
}